// round 1
// baseline (speedup 1.0000x reference)
#include <cuda_runtime.h>
#include <cuda_fp16.h>

#define NGRIDS 64
#define DIMSZ  64
#define VOX    (DIMSZ*DIMSZ*DIMSZ)      // 262144
#define NPTS   (1<<19)
#define NN     64                       // neurons
#define DIN    128                      // 64 grids * 2 feats

// 64 MB interleaved half2 feature buffer: g_feat[g*VOX + idx] = (ch0, ch1)
__device__ __half2 g_feat[NGRIDS * VOX];
// per-grid affine params: rows of A (3x4: a0,a1,a2,b) mapping x -> grid coords
__device__ float g_params[NGRIDS * 12];

__global__ void prep_params_kernel(const float* __restrict__ r,
                                   const float* __restrict__ s,
                                   const float* __restrict__ t) {
    int g = threadIdx.x;
    if (g >= NGRIDS) return;
    float qw = r[4*g+0], qx = r[4*g+1], qy = r[4*g+2], qz = r[4*g+3];
    float inv = 1.0f / sqrtf(qw*qw + qx*qx + qy*qy + qz*qz);
    qw *= inv; qx *= inv; qy *= inv; qz *= inv;
    float R[9];
    R[0] = 1.f - 2.f*(qy*qy + qz*qz); R[1] = 2.f*(qx*qy - qw*qz); R[2] = 2.f*(qx*qz + qw*qy);
    R[3] = 2.f*(qx*qy + qw*qz); R[4] = 1.f - 2.f*(qx*qx + qz*qz); R[5] = 2.f*(qy*qz - qw*qx);
    R[6] = 2.f*(qx*qz - qw*qy); R[7] = 2.f*(qy*qz + qw*qx); R[8] = 1.f - 2.f*(qx*qx + qy*qy);
    #pragma unroll
    for (int i = 0; i < 3; i++) {
        float sc = 31.5f * s[3*g + i];
        g_params[g*12 + 4*i + 0] = sc * R[3*i + 0];
        g_params[g*12 + 4*i + 1] = sc * R[3*i + 1];
        g_params[g*12 + 4*i + 2] = sc * R[3*i + 2];
        g_params[g*12 + 4*i + 3] = 31.5f * (t[3*g + i] + 1.0f);
    }
}

// features [G, 2, 64,64,64] f32  ->  g_feat [G, 64^3] half2 (ch0 low, ch1 high)
__global__ void prep_feat_kernel(const float* __restrict__ f) {
    int i = blockIdx.x * blockDim.x + threadIdx.x;   // one per voxel-quad
    const int QUADS = NGRIDS * (VOX / 4);            // 4194304
    if (i >= QUADS) return;
    int g = i >> 16;             // VOX/4 = 65536 quads per grid
    int q = i & 65535;
    const float4* c0 = reinterpret_cast<const float4*>(f + (size_t)g * 2 * VOX);
    const float4* c1 = reinterpret_cast<const float4*>(f + (size_t)g * 2 * VOX + VOX);
    float4 a = c0[q];
    float4 b = c1[q];
    __half2* out = g_feat + (size_t)g * VOX + (size_t)q * 4;
    out[0] = __floats2half2_rn(a.x, b.x);
    out[1] = __floats2half2_rn(a.y, b.y);
    out[2] = __floats2half2_rn(a.z, b.z);
    out[3] = __floats2half2_rn(a.w, b.w);
}

__global__ __launch_bounds__(128, 4)
void amgsrn_main_kernel(const float* __restrict__ x,
                        const float* __restrict__ W0,
                        const float* __restrict__ W1,
                        const float* __restrict__ W2,
                        float* __restrict__ out) {
    extern __shared__ float smem[];
    float* sP   = smem;                  // 768   affine params
    float* sW0t = smem + 768;            // 8192  W0 transposed: [i=0..127][k=0..63]
    float* sW1  = sW0t + 8192;           // 4096  W1 row-major [j][k]
    float* sW2  = sW1 + 4096;            // 64

    int tid = threadIdx.x;
    for (int i = tid; i < NGRIDS*12; i += 128) sP[i] = g_params[i];
    for (int i = tid; i < NN*DIN; i += 128) {    // W0[k][ii] at k*128+ii
        int k = i >> 7, ii = i & 127;
        sW0t[ii*64 + k] = W0[i];
    }
    for (int i = tid; i < NN*NN; i += 128) sW1[i] = W1[i];
    if (tid < NN) sW2[tid] = W2[tid];
    __syncthreads();

    int n = blockIdx.x * 128 + tid;
    if (n >= NPTS) return;
    float px = x[3*n + 0], py = x[3*n + 1], pz = x[3*n + 2];

    float h0[NN];
    #pragma unroll
    for (int k = 0; k < NN; k++) h0[k] = 0.0f;

    #pragma unroll 1
    for (int g = 0; g < NGRIDS; g++) {
        const float* P = sP + g*12;
        float gx = fmaf(P[0], px, fmaf(P[1], py, fmaf(P[2],  pz, P[3])));
        float gy = fmaf(P[4], px, fmaf(P[5], py, fmaf(P[6],  pz, P[7])));
        float gz = fmaf(P[8], px, fmaf(P[9], py, fmaf(P[10], pz, P[11])));

        float xf = floorf(gx), yf = floorf(gy), zf = floorf(gz);
        float fx = gx - xf, fy = gy - yf, fz = gz - zf;
        int ix = (int)xf, iy = (int)yf, iz = (int)zf;

        float wx0 = (ix   >= 0 && ix   < 64) ? (1.0f - fx) : 0.0f;
        float wx1 = (ix+1 >= 0 && ix+1 < 64) ? fx          : 0.0f;
        float wy0 = (iy   >= 0 && iy   < 64) ? (1.0f - fy) : 0.0f;
        float wy1 = (iy+1 >= 0 && iy+1 < 64) ? fy          : 0.0f;
        float wz0 = (iz   >= 0 && iz   < 64) ? (1.0f - fz) : 0.0f;
        float wz1 = (iz+1 >= 0 && iz+1 < 64) ? fz          : 0.0f;

        int cx0 = min(max(ix,   0), 63), cx1 = min(max(ix+1, 0), 63);
        int cy0 = min(max(iy,   0), 63), cy1 = min(max(iy+1, 0), 63);
        int cz0 = min(max(iz,   0), 63), cz1 = min(max(iz+1, 0), 63);

        const __half2* F = g_feat + (size_t)g * VOX;
        int by0 = cy0 * 64, by1 = cy1 * 64;
        int bz0 = cz0 * 4096, bz1 = cz1 * 4096;

        __half2 v000 = __ldg(F + bz0 + by0 + cx0);
        __half2 v001 = __ldg(F + bz0 + by0 + cx1);
        __half2 v010 = __ldg(F + bz0 + by1 + cx0);
        __half2 v011 = __ldg(F + bz0 + by1 + cx1);
        __half2 v100 = __ldg(F + bz1 + by0 + cx0);
        __half2 v101 = __ldg(F + bz1 + by0 + cx1);
        __half2 v110 = __ldg(F + bz1 + by1 + cx0);
        __half2 v111 = __ldg(F + bz1 + by1 + cx1);

        float w00 = wz0*wy0, w01 = wz0*wy1, w10 = wz1*wy0, w11 = wz1*wy1;

        float2 f000 = __half22float2(v000), f001 = __half22float2(v001);
        float2 f010 = __half22float2(v010), f011 = __half22float2(v011);
        float2 f100 = __half22float2(v100), f101 = __half22float2(v101);
        float2 f110 = __half22float2(v110), f111 = __half22float2(v111);

        float c0 = w00*fmaf(wx0, f000.x, wx1*f001.x)
                 + w01*fmaf(wx0, f010.x, wx1*f011.x)
                 + w10*fmaf(wx0, f100.x, wx1*f101.x)
                 + w11*fmaf(wx0, f110.x, wx1*f111.x);
        float c1 = w00*fmaf(wx0, f000.y, wx1*f001.y)
                 + w01*fmaf(wx0, f010.y, wx1*f011.y)
                 + w10*fmaf(wx0, f100.y, wx1*f101.y)
                 + w11*fmaf(wx0, f110.y, wx1*f111.y);

        // fold first layer: h0 += c0 * W0[:, 2g] + c1 * W0[:, 2g+1]
        const float4* ra = reinterpret_cast<const float4*>(sW0t + (2*g)   * 64);
        const float4* rb = reinterpret_cast<const float4*>(sW0t + (2*g+1) * 64);
        #pragma unroll
        for (int k4 = 0; k4 < 16; k4++) {
            float4 wa = ra[k4];
            float4 wb = rb[k4];
            h0[4*k4+0] = fmaf(c0, wa.x, fmaf(c1, wb.x, h0[4*k4+0]));
            h0[4*k4+1] = fmaf(c0, wa.y, fmaf(c1, wb.y, h0[4*k4+1]));
            h0[4*k4+2] = fmaf(c0, wa.z, fmaf(c1, wb.z, h0[4*k4+2]));
            h0[4*k4+3] = fmaf(c0, wa.w, fmaf(c1, wb.w, h0[4*k4+3]));
        }
    }

    #pragma unroll
    for (int k = 0; k < NN; k++) h0[k] = fmaxf(h0[k], 0.0f);

    float o = 0.0f;
    #pragma unroll 1
    for (int j = 0; j < NN; j++) {
        const float4* w = reinterpret_cast<const float4*>(sW1 + j*64);
        float a0 = 0.f, a1 = 0.f, a2 = 0.f, a3 = 0.f;
        #pragma unroll
        for (int k4 = 0; k4 < 16; k4++) {
            float4 ww = w[k4];
            a0 = fmaf(ww.x, h0[4*k4+0], a0);
            a1 = fmaf(ww.y, h0[4*k4+1], a1);
            a2 = fmaf(ww.z, h0[4*k4+2], a2);
            a3 = fmaf(ww.w, h0[4*k4+3], a3);
        }
        float acc = (a0 + a1) + (a2 + a3);
        o = fmaf(sW2[j], fmaxf(acc, 0.0f), o);
    }
    out[n] = o;
}

extern "C" void kernel_launch(void* const* d_in, const int* in_sizes, int n_in,
                              void* d_out, int out_size) {
    const float* x  = (const float*)d_in[0];
    const float* r  = (const float*)d_in[1];
    const float* s  = (const float*)d_in[2];
    const float* t  = (const float*)d_in[3];
    const float* f  = (const float*)d_in[4];
    const float* W0 = (const float*)d_in[5];
    const float* W1 = (const float*)d_in[6];
    const float* W2 = (const float*)d_in[7];
    float* out = (float*)d_out;

    const int SMEM_BYTES = (768 + 8192 + 4096 + 64) * 4;  // 52480
    cudaFuncSetAttribute(amgsrn_main_kernel,
                         cudaFuncAttributeMaxDynamicSharedMemorySize, SMEM_BYTES);

    prep_params_kernel<<<1, 64>>>(r, s, t);
    const int QUADS = NGRIDS * (VOX / 4);
    prep_feat_kernel<<<(QUADS + 255) / 256, 256>>>(f);
    amgsrn_main_kernel<<<NPTS / 128, 128, SMEM_BYTES>>>(x, W0, W1, W2, out);
}

// round 2
// speedup vs baseline: 1.6558x; 1.6558x over previous
#include <cuda_runtime.h>
#include <cuda_fp16.h>

#define NGRIDS 64
#define DIMSZ  64
#define VOX    (DIMSZ*DIMSZ*DIMSZ)      // 262144
#define NPTS   (1<<19)
#define NN     64
#define DIN    128
#define NBINS  32768                    // 32^3 spatial bins

// scratch (__device__ globals — no allocations allowed)
__device__ __half2 g_feat[NGRIDS * VOX];          // 64 MB interleaved (ch0,ch1)
__device__ float   g_params[NGRIDS * 12];
__device__ int     g_hist[NBINS];
__device__ int     g_cnt[NBINS];
__device__ float   g_xs[NPTS], g_ys[NPTS], g_zs[NPTS];
__device__ int     g_ridx[NPTS];

// ---------- packed f32x2 helpers ----------
__device__ __forceinline__ unsigned long long fma2(unsigned long long a,
                                                   unsigned long long b,
                                                   unsigned long long c) {
    unsigned long long d;
    asm("fma.rn.f32x2 %0, %1, %2, %3;" : "=l"(d) : "l"(a), "l"(b), "l"(c));
    return d;
}
__device__ __forceinline__ unsigned long long pack2(float lo, float hi) {
    unsigned long long d;
    asm("mov.b64 %0, {%1, %2};" : "=l"(d) : "f"(lo), "f"(hi));
    return d;
}
__device__ __forceinline__ void unpack2(unsigned long long v, float& lo, float& hi) {
    asm("mov.b64 {%0, %1}, %2;" : "=f"(lo), "=f"(hi) : "l"(v));
}

__device__ __forceinline__ int bin_key(float px, float py, float pz) {
    int kx = min(31, max(0, (int)((px + 1.0f) * 16.0f)));
    int ky = min(31, max(0, (int)((py + 1.0f) * 16.0f)));
    int kz = min(31, max(0, (int)((pz + 1.0f) * 16.0f)));
    return (kz << 10) | (ky << 5) | kx;
}

// ---------- sort pipeline ----------
__global__ void zero_hist_kernel() {
    int i = blockIdx.x * 256 + threadIdx.x;
    if (i < NBINS) g_hist[i] = 0;
}

__global__ void hist_kernel(const float* __restrict__ x) {
    int n = blockIdx.x * 256 + threadIdx.x;
    if (n >= NPTS) return;
    atomicAdd(&g_hist[bin_key(x[3*n], x[3*n+1], x[3*n+2])], 1);
}

__global__ void scan_kernel() {       // 1 block, 1024 threads, 32 items each
    __shared__ int ssum[1024];
    int tid = threadIdx.x;
    int base = tid * 32;
    int local[32];
    int s = 0;
    #pragma unroll
    for (int i = 0; i < 32; i++) { local[i] = s; s += g_hist[base + i]; }
    ssum[tid] = s;
    __syncthreads();
    for (int off = 1; off < 1024; off <<= 1) {
        int v = (tid >= off) ? ssum[tid - off] : 0;
        __syncthreads();
        ssum[tid] += v;
        __syncthreads();
    }
    int pre = (tid > 0) ? ssum[tid - 1] : 0;
    #pragma unroll
    for (int i = 0; i < 32; i++) g_cnt[base + i] = pre + local[i];
}

__global__ void scatter_kernel(const float* __restrict__ x) {
    int n = blockIdx.x * 256 + threadIdx.x;
    if (n >= NPTS) return;
    float px = x[3*n], py = x[3*n+1], pz = x[3*n+2];
    int pos = atomicAdd(&g_cnt[bin_key(px, py, pz)], 1);
    g_xs[pos] = px; g_ys[pos] = py; g_zs[pos] = pz;
    g_ridx[pos] = n;
}

// ---------- prep ----------
__global__ void prep_params_kernel(const float* __restrict__ r,
                                   const float* __restrict__ s,
                                   const float* __restrict__ t) {
    int g = threadIdx.x;
    if (g >= NGRIDS) return;
    float qw = r[4*g+0], qx = r[4*g+1], qy = r[4*g+2], qz = r[4*g+3];
    float inv = 1.0f / sqrtf(qw*qw + qx*qx + qy*qy + qz*qz);
    qw *= inv; qx *= inv; qy *= inv; qz *= inv;
    float R[9];
    R[0] = 1.f - 2.f*(qy*qy + qz*qz); R[1] = 2.f*(qx*qy - qw*qz); R[2] = 2.f*(qx*qz + qw*qy);
    R[3] = 2.f*(qx*qy + qw*qz); R[4] = 1.f - 2.f*(qx*qx + qz*qz); R[5] = 2.f*(qy*qz - qw*qx);
    R[6] = 2.f*(qx*qz - qw*qy); R[7] = 2.f*(qy*qz + qw*qx); R[8] = 1.f - 2.f*(qx*qx + qy*qy);
    #pragma unroll
    for (int i = 0; i < 3; i++) {
        float sc = 31.5f * s[3*g + i];
        g_params[g*12 + 4*i + 0] = sc * R[3*i + 0];
        g_params[g*12 + 4*i + 1] = sc * R[3*i + 1];
        g_params[g*12 + 4*i + 2] = sc * R[3*i + 2];
        g_params[g*12 + 4*i + 3] = 31.5f * (t[3*g + i] + 1.0f);
    }
}

__global__ void prep_feat_kernel(const float* __restrict__ f) {
    int i = blockIdx.x * blockDim.x + threadIdx.x;
    const int QUADS = NGRIDS * (VOX / 4);
    if (i >= QUADS) return;
    int g = i >> 16;
    int q = i & 65535;
    const float4* c0 = reinterpret_cast<const float4*>(f + (size_t)g * 2 * VOX);
    const float4* c1 = reinterpret_cast<const float4*>(f + (size_t)g * 2 * VOX + VOX);
    float4 a = c0[q];
    float4 b = c1[q];
    __half2* out = g_feat + (size_t)g * VOX + (size_t)q * 4;
    out[0] = __floats2half2_rn(a.x, b.x);
    out[1] = __floats2half2_rn(a.y, b.y);
    out[2] = __floats2half2_rn(a.z, b.z);
    out[3] = __floats2half2_rn(a.w, b.w);
}

// ---------- main ----------
__global__ __launch_bounds__(128, 4)
void amgsrn_main_kernel(const float* __restrict__ W0,
                        const float* __restrict__ W1,
                        const float* __restrict__ W2,
                        float* __restrict__ out) {
    extern __shared__ float smem[];
    float* sP   = smem;                  // 768
    float* sW0t = smem + 768;            // 8192  W0^T: [in=0..127][neuron=0..63]
    float* sW1  = sW0t + 8192;           // 4096
    float* sW2  = sW1 + 4096;            // 64

    int tid = threadIdx.x;
    for (int i = tid; i < NGRIDS*12; i += 128) sP[i] = g_params[i];
    for (int i = tid; i < NN*DIN; i += 128) {
        int k = i >> 7, ii = i & 127;
        sW0t[ii*64 + k] = W0[i];
    }
    for (int i = tid; i < NN*NN; i += 128) sW1[i] = W1[i];
    if (tid < NN) sW2[tid] = W2[tid];
    __syncthreads();

    int n = blockIdx.x * 128 + tid;
    if (n >= NPTS) return;
    float px = g_xs[n], py = g_ys[n], pz = g_zs[n];
    int orig = g_ridx[n];

    unsigned long long h2[32];           // packed h0: (2k, 2k+1)
    #pragma unroll
    for (int k = 0; k < 32; k++) h2[k] = 0ull;

    #pragma unroll 1
    for (int g = 0; g < NGRIDS; g++) {
        const float* P = sP + g*12;
        float gx = fmaf(P[0], px, fmaf(P[1], py, fmaf(P[2],  pz, P[3])));
        float gy = fmaf(P[4], px, fmaf(P[5], py, fmaf(P[6],  pz, P[7])));
        float gz = fmaf(P[8], px, fmaf(P[9], py, fmaf(P[10], pz, P[11])));

        float xf = floorf(gx), yf = floorf(gy), zf = floorf(gz);
        float fx = gx - xf, fy = gy - yf, fz = gz - zf;
        int ix = (int)xf, iy = (int)yf, iz = (int)zf;

        float wx0 = (ix   >= 0 && ix   < 64) ? (1.0f - fx) : 0.0f;
        float wx1 = (ix+1 >= 0 && ix+1 < 64) ? fx          : 0.0f;
        float wy0 = (iy   >= 0 && iy   < 64) ? (1.0f - fy) : 0.0f;
        float wy1 = (iy+1 >= 0 && iy+1 < 64) ? fy          : 0.0f;
        float wz0 = (iz   >= 0 && iz   < 64) ? (1.0f - fz) : 0.0f;
        float wz1 = (iz+1 >= 0 && iz+1 < 64) ? fz          : 0.0f;

        int cx0 = min(max(ix,   0), 63), cx1 = min(max(ix+1, 0), 63);
        int cy0 = min(max(iy,   0), 63), cy1 = min(max(iy+1, 0), 63);
        int cz0 = min(max(iz,   0), 63), cz1 = min(max(iz+1, 0), 63);

        const __half2* F = g_feat + (size_t)g * VOX;
        int by0 = cy0 * 64, by1 = cy1 * 64;
        int bz0 = cz0 * 4096, bz1 = cz1 * 4096;

        __half2 v000 = __ldg(F + bz0 + by0 + cx0);
        __half2 v001 = __ldg(F + bz0 + by0 + cx1);
        __half2 v010 = __ldg(F + bz0 + by1 + cx0);
        __half2 v011 = __ldg(F + bz0 + by1 + cx1);
        __half2 v100 = __ldg(F + bz1 + by0 + cx0);
        __half2 v101 = __ldg(F + bz1 + by0 + cx1);
        __half2 v110 = __ldg(F + bz1 + by1 + cx0);
        __half2 v111 = __ldg(F + bz1 + by1 + cx1);

        float w00 = wz0*wy0, w01 = wz0*wy1, w10 = wz1*wy0, w11 = wz1*wy1;

        float2 f000 = __half22float2(v000), f001 = __half22float2(v001);
        float2 f010 = __half22float2(v010), f011 = __half22float2(v011);
        float2 f100 = __half22float2(v100), f101 = __half22float2(v101);
        float2 f110 = __half22float2(v110), f111 = __half22float2(v111);

        float c0 = w00*fmaf(wx0, f000.x, wx1*f001.x)
                 + w01*fmaf(wx0, f010.x, wx1*f011.x)
                 + w10*fmaf(wx0, f100.x, wx1*f101.x)
                 + w11*fmaf(wx0, f110.x, wx1*f111.x);
        float c1 = w00*fmaf(wx0, f000.y, wx1*f001.y)
                 + w01*fmaf(wx0, f010.y, wx1*f011.y)
                 + w10*fmaf(wx0, f100.y, wx1*f101.y)
                 + w11*fmaf(wx0, f110.y, wx1*f111.y);

        // h0 += c0 * W0[:, 2g] + c1 * W0[:, 2g+1]   (packed f32x2)
        unsigned long long c00 = pack2(c0, c0);
        unsigned long long c11 = pack2(c1, c1);
        const ulonglong2* ra = reinterpret_cast<const ulonglong2*>(sW0t + (2*g)   * 64);
        const ulonglong2* rb = reinterpret_cast<const ulonglong2*>(sW0t + (2*g+1) * 64);
        #pragma unroll
        for (int k4 = 0; k4 < 16; k4++) {
            ulonglong2 wa = ra[k4];
            ulonglong2 wb = rb[k4];
            h2[2*k4+0] = fma2(c00, wa.x, fma2(c11, wb.x, h2[2*k4+0]));
            h2[2*k4+1] = fma2(c00, wa.y, fma2(c11, wb.y, h2[2*k4+1]));
        }
    }

    // ReLU
    #pragma unroll
    for (int k = 0; k < 32; k++) {
        float lo, hi;
        unpack2(h2[k], lo, hi);
        h2[k] = pack2(fmaxf(lo, 0.0f), fmaxf(hi, 0.0f));
    }

    float o = 0.0f;
    #pragma unroll 1
    for (int j = 0; j < NN; j++) {
        const ulonglong2* w = reinterpret_cast<const ulonglong2*>(sW1 + j*64);
        unsigned long long a0 = 0ull, a1 = 0ull;
        #pragma unroll
        for (int k4 = 0; k4 < 16; k4++) {
            ulonglong2 ww = w[k4];
            a0 = fma2(ww.x, h2[2*k4+0], a0);
            a1 = fma2(ww.y, h2[2*k4+1], a1);
        }
        float l0, h0v, l1, h1v;
        unpack2(a0, l0, h0v);
        unpack2(a1, l1, h1v);
        float acc = (l0 + l1) + (h0v + h1v);
        o = fmaf(sW2[j], fmaxf(acc, 0.0f), o);
    }
    out[orig] = o;
}

extern "C" void kernel_launch(void* const* d_in, const int* in_sizes, int n_in,
                              void* d_out, int out_size) {
    const float* x  = (const float*)d_in[0];
    const float* r  = (const float*)d_in[1];
    const float* s  = (const float*)d_in[2];
    const float* t  = (const float*)d_in[3];
    const float* f  = (const float*)d_in[4];
    const float* W0 = (const float*)d_in[5];
    const float* W1 = (const float*)d_in[6];
    const float* W2 = (const float*)d_in[7];
    float* out = (float*)d_out;

    const int SMEM_BYTES = (768 + 8192 + 4096 + 64) * 4;  // 52480
    cudaFuncSetAttribute(amgsrn_main_kernel,
                         cudaFuncAttributeMaxDynamicSharedMemorySize, SMEM_BYTES);

    zero_hist_kernel<<<(NBINS + 255) / 256, 256>>>();
    hist_kernel<<<(NPTS + 255) / 256, 256>>>(x);
    scan_kernel<<<1, 1024>>>();
    scatter_kernel<<<(NPTS + 255) / 256, 256>>>(x);
    prep_params_kernel<<<1, 64>>>(r, s, t);
    const int QUADS = NGRIDS * (VOX / 4);
    prep_feat_kernel<<<(QUADS + 255) / 256, 256>>>(f);
    amgsrn_main_kernel<<<NPTS / 128, 128, SMEM_BYTES>>>(W0, W1, W2, out);
}

// round 3
// speedup vs baseline: 1.7928x; 1.0828x over previous
#include <cuda_runtime.h>
#include <cuda_fp16.h>

#define NGRIDS 64
#define DIMSZ  64
#define VOX    (DIMSZ*DIMSZ*DIMSZ)      // 262144
#define NPTS   (1<<19)
#define NN     64
#define DIN    128
#define NBINS  32768                    // 32^3 spatial bins

// 256 MB corner-pair buffer: voxel (g,z,y,x) holds 16B =
//   half2(ch0[x,y], ch0[x+1,y]), half2(ch0[x,y+1], ch0[x+1,y+1]),
//   half2(ch1[x,y], ch1[x+1,y]), half2(ch1[x,y+1], ch1[x+1,y+1])
__device__ uint4   g_feat[NGRIDS * VOX];
__device__ float   g_params[NGRIDS * 12];
__device__ int     g_hist[NBINS];
__device__ int     g_cnt[NBINS];
__device__ float   g_xs[NPTS], g_ys[NPTS], g_zs[NPTS];
__device__ int     g_ridx[NPTS];

// ---------- packed f32x2 helpers ----------
__device__ __forceinline__ unsigned long long fma2(unsigned long long a,
                                                   unsigned long long b,
                                                   unsigned long long c) {
    unsigned long long d;
    asm("fma.rn.f32x2 %0, %1, %2, %3;" : "=l"(d) : "l"(a), "l"(b), "l"(c));
    return d;
}
__device__ __forceinline__ unsigned long long pack2(float lo, float hi) {
    unsigned long long d;
    asm("mov.b64 %0, {%1, %2};" : "=l"(d) : "f"(lo), "f"(hi));
    return d;
}
__device__ __forceinline__ void unpack2(unsigned long long v, float& lo, float& hi) {
    asm("mov.b64 {%0, %1}, %2;" : "=f"(lo), "=f"(hi) : "l"(v));
}

__device__ __forceinline__ int bin_key(float px, float py, float pz) {
    int kx = min(31, max(0, (int)((px + 1.0f) * 16.0f)));
    int ky = min(31, max(0, (int)((py + 1.0f) * 16.0f)));
    int kz = min(31, max(0, (int)((pz + 1.0f) * 16.0f)));
    return (kz << 10) | (ky << 5) | kx;
}

// ---------- sort pipeline ----------
__global__ void zero_hist_kernel() {
    int i = blockIdx.x * 256 + threadIdx.x;
    if (i < NBINS) g_hist[i] = 0;
}

__global__ void hist_kernel(const float* __restrict__ x) {
    int n = blockIdx.x * 256 + threadIdx.x;
    if (n >= NPTS) return;
    atomicAdd(&g_hist[bin_key(x[3*n], x[3*n+1], x[3*n+2])], 1);
}

// block 0: exclusive scan of g_hist; block 1: affine params
__global__ void scan_params_kernel(const float* __restrict__ r,
                                   const float* __restrict__ s,
                                   const float* __restrict__ t) {
    if (blockIdx.x == 1) {
        int g = threadIdx.x;
        if (g >= NGRIDS) return;
        float qw = r[4*g+0], qx = r[4*g+1], qy = r[4*g+2], qz = r[4*g+3];
        float inv = 1.0f / sqrtf(qw*qw + qx*qx + qy*qy + qz*qz);
        qw *= inv; qx *= inv; qy *= inv; qz *= inv;
        float R[9];
        R[0] = 1.f - 2.f*(qy*qy + qz*qz); R[1] = 2.f*(qx*qy - qw*qz); R[2] = 2.f*(qx*qz + qw*qy);
        R[3] = 2.f*(qx*qy + qw*qz); R[4] = 1.f - 2.f*(qx*qx + qz*qz); R[5] = 2.f*(qy*qz - qw*qx);
        R[6] = 2.f*(qx*qz - qw*qy); R[7] = 2.f*(qy*qz + qw*qx); R[8] = 1.f - 2.f*(qx*qx + qy*qy);
        #pragma unroll
        for (int i = 0; i < 3; i++) {
            float sc = 31.5f * s[3*g + i];
            g_params[g*12 + 4*i + 0] = sc * R[3*i + 0];
            g_params[g*12 + 4*i + 1] = sc * R[3*i + 1];
            g_params[g*12 + 4*i + 2] = sc * R[3*i + 2];
            g_params[g*12 + 4*i + 3] = 31.5f * (t[3*g + i] + 1.0f);
        }
        return;
    }
    __shared__ int ssum[1024];
    int tid = threadIdx.x;
    int base = tid * 32;
    int local[32];
    int acc = 0;
    #pragma unroll
    for (int i = 0; i < 32; i++) { local[i] = acc; acc += g_hist[base + i]; }
    ssum[tid] = acc;
    __syncthreads();
    for (int off = 1; off < 1024; off <<= 1) {
        int v = (tid >= off) ? ssum[tid - off] : 0;
        __syncthreads();
        ssum[tid] += v;
        __syncthreads();
    }
    int pre = (tid > 0) ? ssum[tid - 1] : 0;
    #pragma unroll
    for (int i = 0; i < 32; i++) g_cnt[base + i] = pre + local[i];
}

__global__ void scatter_kernel(const float* __restrict__ x) {
    int n = blockIdx.x * 256 + threadIdx.x;
    if (n >= NPTS) return;
    float px = x[3*n], py = x[3*n+1], pz = x[3*n+2];
    int pos = atomicAdd(&g_cnt[bin_key(px, py, pz)], 1);
    g_xs[pos] = px; g_ys[pos] = py; g_zs[pos] = pz;
    g_ridx[pos] = n;
}

// ---------- feature prep: build corner-pair 16B voxels ----------
__global__ void prep_feat_kernel(const float* __restrict__ f) {
    int i = blockIdx.x * 256 + threadIdx.x;     // one per voxel
    if (i >= NGRIDS * VOX) return;
    int g   = i >> 18;
    int rem = i & (VOX - 1);
    int z = rem >> 12;
    int y = (rem >> 6) & 63;
    int xx = rem & 63;
    int xp = min(xx + 1, 63);
    int yp = min(y + 1, 63);
    const float* B0 = f + (size_t)g * 2 * VOX;
    const float* B1 = B0 + VOX;
    int r0 = (z << 12) + (y  << 6);
    int r1 = (z << 12) + (yp << 6);
    __half2 w0 = __floats2half2_rn(B0[r0 + xx], B0[r0 + xp]);
    __half2 w1 = __floats2half2_rn(B0[r1 + xx], B0[r1 + xp]);
    __half2 w2 = __floats2half2_rn(B1[r0 + xx], B1[r0 + xp]);
    __half2 w3 = __floats2half2_rn(B1[r1 + xx], B1[r1 + xp]);
    uint4 o;
    o.x = *(unsigned int*)&w0;
    o.y = *(unsigned int*)&w1;
    o.z = *(unsigned int*)&w2;
    o.w = *(unsigned int*)&w3;
    g_feat[i] = o;
}

// slot + pair-weights for a paired axis (x or y):
// contribution = wlo * f[slot] + whi * f[slot+1 (clamped into pair)]
__device__ __forceinline__ void axis_pair(float gc, int& slot, float& wlo, float& whi) {
    float cf = floorf(gc);
    float fr = gc - cf;
    int ic = (int)cf;
    slot = min(max(ic, 0), 63);
    bool v0 = (ic >= 0) & (ic < 64);
    wlo = v0 ? (1.0f - fr) : ((ic == -1) ? fr : 0.0f);
    whi = (v0 & (ic < 63)) ? fr : 0.0f;
}

// ---------- main ----------
__global__ __launch_bounds__(128, 4)
void amgsrn_main_kernel(const float* __restrict__ W0,
                        const float* __restrict__ W1,
                        const float* __restrict__ W2,
                        float* __restrict__ out) {
    extern __shared__ float smem[];
    float* sP   = smem;                  // 768
    float* sW0t = smem + 768;            // 8192  W0^T: [in=0..127][neuron=0..63]
    float* sW1  = sW0t + 8192;           // 4096
    float* sW2  = sW1 + 4096;            // 64

    int tid = threadIdx.x;
    for (int i = tid; i < NGRIDS*12; i += 128) sP[i] = g_params[i];
    for (int i = tid; i < NN*DIN; i += 128) {
        int k = i >> 7, ii = i & 127;
        sW0t[ii*64 + k] = W0[i];
    }
    for (int i = tid; i < NN*NN; i += 128) sW1[i] = W1[i];
    if (tid < NN) sW2[tid] = W2[tid];
    __syncthreads();

    int n = blockIdx.x * 128 + tid;
    if (n >= NPTS) return;
    float px = g_xs[n], py = g_ys[n], pz = g_zs[n];
    int orig = g_ridx[n];

    unsigned long long h2[32];
    #pragma unroll
    for (int k = 0; k < 32; k++) h2[k] = 0ull;

    #pragma unroll 1
    for (int g = 0; g < NGRIDS; g++) {
        const float* P = sP + g*12;
        float gx = fmaf(P[0], px, fmaf(P[1], py, fmaf(P[2],  pz, P[3])));
        float gy = fmaf(P[4], px, fmaf(P[5], py, fmaf(P[6],  pz, P[7])));
        float gz = fmaf(P[8], px, fmaf(P[9], py, fmaf(P[10], pz, P[11])));

        int sx, sy;
        float wxlo, wxhi, wylo, wyhi;
        axis_pair(gx, sx, wxlo, wxhi);
        axis_pair(gy, sy, wylo, wyhi);

        float zf = floorf(gz);
        float fz = gz - zf;
        int iz = (int)zf;
        float wz0 = (iz   >= 0 && iz   < 64) ? (1.0f - fz) : 0.0f;
        float wz1 = (iz+1 >= 0 && iz+1 < 64) ? fz          : 0.0f;
        int cz0 = min(max(iz,   0), 63);
        int cz1 = min(max(iz+1, 0), 63);

        const uint4* F = g_feat + ((size_t)g << 18);
        int base = (sy << 6) + sx;
        uint4 v0 = __ldg(F + (cz0 << 12) + base);
        uint4 v1 = __ldg(F + (cz1 << 12) + base);

        float c0, c1;
        {
            float2 p0 = __half22float2(*(__half2*)&v0.x);
            float2 p1 = __half22float2(*(__half2*)&v0.y);
            float2 q0 = __half22float2(*(__half2*)&v0.z);
            float2 q1 = __half22float2(*(__half2*)&v0.w);
            float r0 = fmaf(wxlo, p0.x, wxhi * p0.y);
            float r1 = fmaf(wxlo, p1.x, wxhi * p1.y);
            float s0 = fmaf(wxlo, q0.x, wxhi * q0.y);
            float s1 = fmaf(wxlo, q1.x, wxhi * q1.y);
            c0 = wz0 * fmaf(wylo, r0, wyhi * r1);
            c1 = wz0 * fmaf(wylo, s0, wyhi * s1);
        }
        {
            float2 p0 = __half22float2(*(__half2*)&v1.x);
            float2 p1 = __half22float2(*(__half2*)&v1.y);
            float2 q0 = __half22float2(*(__half2*)&v1.z);
            float2 q1 = __half22float2(*(__half2*)&v1.w);
            float r0 = fmaf(wxlo, p0.x, wxhi * p0.y);
            float r1 = fmaf(wxlo, p1.x, wxhi * p1.y);
            float s0 = fmaf(wxlo, q0.x, wxhi * q0.y);
            float s1 = fmaf(wxlo, q1.x, wxhi * q1.y);
            c0 = fmaf(wz1, fmaf(wylo, r0, wyhi * r1), c0);
            c1 = fmaf(wz1, fmaf(wylo, s0, wyhi * s1), c1);
        }

        // h0 += c0 * W0[:, 2g] + c1 * W0[:, 2g+1]   (packed f32x2)
        unsigned long long c00 = pack2(c0, c0);
        unsigned long long c11 = pack2(c1, c1);
        const ulonglong2* ra = reinterpret_cast<const ulonglong2*>(sW0t + (2*g)   * 64);
        const ulonglong2* rb = reinterpret_cast<const ulonglong2*>(sW0t + (2*g+1) * 64);
        #pragma unroll
        for (int k4 = 0; k4 < 16; k4++) {
            ulonglong2 wa = ra[k4];
            ulonglong2 wb = rb[k4];
            h2[2*k4+0] = fma2(c00, wa.x, fma2(c11, wb.x, h2[2*k4+0]));
            h2[2*k4+1] = fma2(c00, wa.y, fma2(c11, wb.y, h2[2*k4+1]));
        }
    }

    // ReLU
    #pragma unroll
    for (int k = 0; k < 32; k++) {
        float lo, hi;
        unpack2(h2[k], lo, hi);
        h2[k] = pack2(fmaxf(lo, 0.0f), fmaxf(hi, 0.0f));
    }

    float o = 0.0f;
    #pragma unroll 1
    for (int j = 0; j < NN; j++) {
        const ulonglong2* w = reinterpret_cast<const ulonglong2*>(sW1 + j*64);
        unsigned long long a0 = 0ull, a1 = 0ull;
        #pragma unroll
        for (int k4 = 0; k4 < 16; k4++) {
            ulonglong2 ww = w[k4];
            a0 = fma2(ww.x, h2[2*k4+0], a0);
            a1 = fma2(ww.y, h2[2*k4+1], a1);
        }
        float l0, h0v, l1, h1v;
        unpack2(a0, l0, h0v);
        unpack2(a1, l1, h1v);
        float acc = (l0 + l1) + (h0v + h1v);
        o = fmaf(sW2[j], fmaxf(acc, 0.0f), o);
    }
    out[orig] = o;
}

extern "C" void kernel_launch(void* const* d_in, const int* in_sizes, int n_in,
                              void* d_out, int out_size) {
    const float* x  = (const float*)d_in[0];
    const float* r  = (const float*)d_in[1];
    const float* s  = (const float*)d_in[2];
    const float* t  = (const float*)d_in[3];
    const float* f  = (const float*)d_in[4];
    const float* W0 = (const float*)d_in[5];
    const float* W1 = (const float*)d_in[6];
    const float* W2 = (const float*)d_in[7];
    float* out = (float*)d_out;

    const int SMEM_BYTES = (768 + 8192 + 4096 + 64) * 4;  // 52480
    cudaFuncSetAttribute(amgsrn_main_kernel,
                         cudaFuncAttributeMaxDynamicSharedMemorySize, SMEM_BYTES);

    zero_hist_kernel<<<(NBINS + 255) / 256, 256>>>();            // 1
    hist_kernel<<<(NPTS + 255) / 256, 256>>>(x);                 // 2
    scan_params_kernel<<<2, 1024>>>(r, s, t);                    // 3
    prep_feat_kernel<<<(NGRIDS * VOX + 255) / 256, 256>>>(f);    // 4 (ncu capture slot)
    scatter_kernel<<<(NPTS + 255) / 256, 256>>>(x);              // 5
    amgsrn_main_kernel<<<NPTS / 128, 128, SMEM_BYTES>>>(W0, W1, W2, out);  // 6
}